// round 1
// baseline (speedup 1.0000x reference)
#include <cuda_runtime.h>

#define BATCH 32768
#define NCH   256
#define FLAT  3072
#define NRED  152          // 16 first moments + 136 upper-triangle second moments
#define NBLK_MOM 128
#define EPSV  1e-5f

// ---------------- device scratch (no allocations allowed) ----------------
__device__ float g_part[NBLK_MOM][NRED];   // per-block partial moment sums
__device__ float g_wscaled[NCH * 16];      // a[c] * conv_w[c]
__device__ float g_shift[NCH];             // beta[c] - a[c]*mean_raw[c]
__device__ float g_h[BATCH * FLAT];        // post-ReLU hidden (B,3072), 402 MB

// =========================================================================
// K1: patch moments.  For each board: 12 patches of 16 values.
//   S1[k]   = sum_{b,p} patch_k
//   S2[k,l] = sum_{b,p} patch_k * patch_l   (upper triangle, 136 values)
// Deterministic: warp shuffle reduce -> smem -> per-block partial in g_part.
// =========================================================================
__global__ void k_moments(const float* __restrict__ x)
{
    int b = blockIdx.x * 256 + threadIdx.x;   // grid covers exactly BATCH
    const float* xb = x + b * 42;
    float xv[42];
#pragma unroll
    for (int i = 0; i < 42; i++) xv[i] = xb[i];

    __shared__ float red[8][NRED];
    int lane = threadIdx.x & 31;
    int warp = threadIdx.x >> 5;

    int idx = 0;
    // first moments
#pragma unroll
    for (int k = 0; k < 16; k++) {
        float s = 0.f;
#pragma unroll
        for (int r = 0; r < 3; r++)
#pragma unroll
            for (int c = 0; c < 4; c++)
                s += xv[(r + (k >> 2)) * 7 + (c + (k & 3))];
#pragma unroll
        for (int o = 16; o; o >>= 1) s += __shfl_xor_sync(0xffffffffu, s, o);
        if (lane == 0) red[warp][idx] = s;
        idx++;
    }
    // second moments (upper triangle)
#pragma unroll
    for (int k = 0; k < 16; k++) {
#pragma unroll
        for (int l = k; l < 16; l++) {
            float s = 0.f;
#pragma unroll
            for (int r = 0; r < 3; r++)
#pragma unroll
                for (int c = 0; c < 4; c++)
                    s += xv[(r + (k >> 2)) * 7 + (c + (k & 3))] *
                         xv[(r + (l >> 2)) * 7 + (c + (l & 3))];
#pragma unroll
            for (int o = 16; o; o >>= 1) s += __shfl_xor_sync(0xffffffffu, s, o);
            if (lane == 0) red[warp][idx] = s;
            idx++;
        }
    }
    __syncthreads();
    if (threadIdx.x < NRED) {
        float s = 0.f;
#pragma unroll
        for (int w = 0; w < 8; w++) s += red[w][threadIdx.x];
        g_part[blockIdx.x][threadIdx.x] = s;
    }
}

// =========================================================================
// K2: finalize BN fold.  mean_raw[c] = w_c . m1 ; var = w_c^T M2 w_c - mean^2
// (conv bias cancels exactly through batch-norm).
//   g_wscaled[c] = a * w_c,  g_shift[c] = beta - a*mean_raw,  a = gamma*rsqrt(var+eps)
// =========================================================================
__global__ void k_finalize(const float* __restrict__ conv_w,
                           const float* __restrict__ bn_gamma,
                           const float* __restrict__ bn_beta)
{
    __shared__ float S[NRED];
    int t = threadIdx.x;
    if (t < NRED) {
        float s = 0.f;
        for (int bl = 0; bl < NBLK_MOM; bl++) s += g_part[bl][t];
        S[t] = s * (1.f / (12.f * (float)BATCH));
    }
    __syncthreads();

    if (t < NCH) {
        float w[16];
#pragma unroll
        for (int i = 0; i < 16; i++) w[i] = conv_w[t * 16 + i];
        float mraw = 0.f;
#pragma unroll
        for (int i = 0; i < 16; i++) mraw += w[i] * S[i];
        float q = 0.f;
        int idx = 16;
#pragma unroll
        for (int k = 0; k < 16; k++) {
#pragma unroll
            for (int l = k; l < 16; l++) {
                float coef = (k == l) ? (w[k] * w[l]) : (2.f * w[k] * w[l]);
                q += coef * S[idx];
                idx++;
            }
        }
        float var = q - mraw * mraw;
        float a = bn_gamma[t] * rsqrtf(var + EPSV);
#pragma unroll
        for (int i = 0; i < 16; i++) g_wscaled[t * 16 + i] = a * w[i];
        g_shift[t] = bn_beta[t] - a * mraw;
    }
}

// =========================================================================
// K3: fused conv + folded-BN + ReLU -> g_h (B, 3072).
// One block per board, one thread per channel.
// =========================================================================
__global__ void k_conv(const float* __restrict__ x)
{
    int b = blockIdx.x;
    int c = threadIdx.x;
    __shared__ float xs[42];
    if (c < 42) xs[c] = x[b * 42 + c];
    __syncthreads();

    float w[16];
    const float4* wp = reinterpret_cast<const float4*>(&g_wscaled[c * 16]);
#pragma unroll
    for (int i = 0; i < 4; i++) {
        float4 v = wp[i];
        w[i * 4 + 0] = v.x; w[i * 4 + 1] = v.y; w[i * 4 + 2] = v.z; w[i * 4 + 3] = v.w;
    }
    float shift = g_shift[c];
    float* out = g_h + (size_t)b * FLAT + c * 12;

#pragma unroll
    for (int r = 0; r < 3; r++) {
#pragma unroll
        for (int s = 0; s < 4; s++) {
            float acc = shift;
#pragma unroll
            for (int i = 0; i < 4; i++)
#pragma unroll
                for (int j = 0; j < 4; j++)
                    acc += w[i * 4 + j] * xs[(r + i) * 7 + (s + j)];
            out[r * 4 + s] = fmaxf(acc, 0.f);
        }
    }
}

// =========================================================================
// K4: fused GEMM (B,3072)@(3072,128) + heads epilogue.
// Block: 64 boards x 128 outputs (n<64: policy fc1, n>=64: value fc1).
// 256 threads; thread tile 8(m) x 4(n); K chunk = 32, double-buffered smem.
// Epilogue: bias+ReLU -> layer2 (64->32 both heads, ReLU) -> layer3 + softmax/tanh.
// =========================================================================
#define MB 64
#define KC 32
#define NCHUNK (FLAT / KC)   // 96

__global__ __launch_bounds__(256) void k_main(
    const float* __restrict__ pw1, const float* __restrict__ pb1,
    const float* __restrict__ pw2, const float* __restrict__ pb2,
    const float* __restrict__ pw3, const float* __restrict__ pb3,
    const float* __restrict__ vw1, const float* __restrict__ vb1,
    const float* __restrict__ vw2, const float* __restrict__ vb2,
    const float* __restrict__ vw3, const float* __restrict__ vb3,
    float* __restrict__ out)
{
    __shared__ float pool[12288];   // 48 KB: hs[2][32][64] | ws[2][32][128]
    float* hs[2] = { pool, pool + 2048 };
    float* ws[2] = { pool + 4096, pool + 8192 };

    const int tid = threadIdx.x;
    const int ty = tid >> 5;        // 0..7  -> boards 8*ty..8*ty+7
    const int tx = tid & 31;        // 0..31 -> outputs 4*tx..4*tx+3
    const int m0 = blockIdx.x * MB;

    // ---- tile-load lanes ----
    const int hrow = tid >> 2;            // 0..63
    const int hc4  = (tid & 3) * 2;       // 0,2,4,6  (two float4 per thread)

    float acc[8][4];
#pragma unroll
    for (int i = 0; i < 8; i++)
#pragma unroll
        for (int j = 0; j < 4; j++) acc[i][j] = 0.f;

    float4 rh[2], rw[4];

    // prefetch chunk 0
    {
        const float* hp = &g_h[(size_t)(m0 + hrow) * FLAT + 0];
        rh[0] = *reinterpret_cast<const float4*>(hp + hc4 * 4);
        rh[1] = *reinterpret_cast<const float4*>(hp + (hc4 + 1) * 4);
#pragma unroll
        for (int j = 0; j < 4; j++) {
            int f4 = tid + j * 256;
            int k = f4 >> 5, c4 = f4 & 31;
            const float* src = (c4 < 16) ? &pw1[(size_t)k * 64 + c4 * 4]
                                         : &vw1[(size_t)k * 64 + (c4 - 16) * 4];
            rw[j] = *reinterpret_cast<const float4*>(src);
        }
    }
    // store chunk 0 into buffer 0
    {
        float hv[8] = { rh[0].x, rh[0].y, rh[0].z, rh[0].w,
                        rh[1].x, rh[1].y, rh[1].z, rh[1].w };
#pragma unroll
        for (int u = 0; u < 8; u++)
            hs[0][(hc4 * 4 + u) * 64 + hrow] = hv[u];
#pragma unroll
        for (int j = 0; j < 4; j++) {
            int f4 = tid + j * 256;
            int k = f4 >> 5, c4 = f4 & 31;
            *reinterpret_cast<float4*>(&ws[0][k * 128 + c4 * 4]) = rw[j];
        }
    }
    __syncthreads();

    for (int ch = 0; ch < NCHUNK; ch++) {
        int buf = ch & 1;
        // prefetch next chunk into registers
        if (ch + 1 < NCHUNK) {
            int kc = (ch + 1) * KC;
            const float* hp = &g_h[(size_t)(m0 + hrow) * FLAT + kc];
            rh[0] = *reinterpret_cast<const float4*>(hp + hc4 * 4);
            rh[1] = *reinterpret_cast<const float4*>(hp + (hc4 + 1) * 4);
#pragma unroll
            for (int j = 0; j < 4; j++) {
                int f4 = tid + j * 256;
                int k = f4 >> 5, c4 = f4 & 31;
                const float* src = (c4 < 16) ? &pw1[(size_t)(kc + k) * 64 + c4 * 4]
                                             : &vw1[(size_t)(kc + k) * 64 + (c4 - 16) * 4];
                rw[j] = *reinterpret_cast<const float4*>(src);
            }
        }
        // compute on current buffer
        const float* hb = hs[buf];
        const float* wb = ws[buf];
#pragma unroll 8
        for (int k = 0; k < KC; k++) {
            float4 b4 = *reinterpret_cast<const float4*>(&wb[k * 128 + 4 * tx]);
            float4 a0 = *reinterpret_cast<const float4*>(&hb[k * 64 + 8 * ty]);
            float4 a1 = *reinterpret_cast<const float4*>(&hb[k * 64 + 8 * ty + 4]);
            float a[8] = { a0.x, a0.y, a0.z, a0.w, a1.x, a1.y, a1.z, a1.w };
            float bb[4] = { b4.x, b4.y, b4.z, b4.w };
#pragma unroll
            for (int i = 0; i < 8; i++)
#pragma unroll
                for (int j = 0; j < 4; j++)
                    acc[i][j] += a[i] * bb[j];
        }
        __syncthreads();
        // store prefetched regs into the other buffer
        if (ch + 1 < NCHUNK) {
            int nb = buf ^ 1;
            float hv[8] = { rh[0].x, rh[0].y, rh[0].z, rh[0].w,
                            rh[1].x, rh[1].y, rh[1].z, rh[1].w };
#pragma unroll
            for (int u = 0; u < 8; u++)
                hs[nb][(hc4 * 4 + u) * 64 + hrow] = hv[u];
#pragma unroll
            for (int j = 0; j < 4; j++) {
                int f4 = tid + j * 256;
                int k = f4 >> 5, c4 = f4 & 31;
                *reinterpret_cast<float4*>(&ws[nb][k * 128 + c4 * 4]) = rw[j];
            }
        }
        __syncthreads();
    }

    // ---------------- epilogue ----------------
    // h1[m][n] = relu(acc + bias)   (pool[0..8191])
    {
        int n0 = 4 * tx;
        float b0 = (n0 < 64) ? pb1[n0 + 0] : vb1[n0 - 64 + 0];
        float b1 = (n0 < 64) ? pb1[n0 + 1] : vb1[n0 - 64 + 1];
        float b2 = (n0 < 64) ? pb1[n0 + 2] : vb1[n0 - 64 + 2];
        float b3 = (n0 < 64) ? pb1[n0 + 3] : vb1[n0 - 64 + 3];
#pragma unroll
        for (int i = 0; i < 8; i++) {
            int m = 8 * ty + i;
            float4 v;
            v.x = fmaxf(acc[i][0] + b0, 0.f);
            v.y = fmaxf(acc[i][1] + b1, 0.f);
            v.z = fmaxf(acc[i][2] + b2, 0.f);
            v.w = fmaxf(acc[i][3] + b3, 0.f);
            *reinterpret_cast<float4*>(&pool[m * 128 + n0]) = v;
        }
    }
    __syncthreads();

    // layer2: 64 boards x (32 policy + 32 value) outputs -> pool[8192..12287]
    float* h2 = pool + 8192;
#pragma unroll
    for (int it = 0; it < 16; it++) {
        int idx = it * 256 + tid;          // 0..4095
        int bd = idx >> 6;
        int o  = idx & 63;
        float s;
        if (o < 32) {
            s = pb2[o];
            const float* h1b = &pool[bd * 128];
#pragma unroll 8
            for (int k = 0; k < 64; k++) s += h1b[k] * pw2[k * 32 + o];
        } else {
            int oo = o - 32;
            s = vb2[oo];
            const float* h1b = &pool[bd * 128 + 64];
#pragma unroll 8
            for (int k = 0; k < 64; k++) s += h1b[k] * vw2[k * 32 + oo];
        }
        h2[bd * 64 + o] = fmaxf(s, 0.f);
    }
    __syncthreads();

    // layer3 + softmax / tanh : one thread per board
    if (tid < MB) {
        int gb = m0 + tid;
        const float* hp = &h2[tid * 64];
        float lg[7];
#pragma unroll
        for (int j = 0; j < 7; j++) {
            float s = pb3[j];
#pragma unroll
            for (int k = 0; k < 32; k++) s += hp[k] * pw3[k * 7 + j];
            lg[j] = s;
        }
        float mx = lg[0];
#pragma unroll
        for (int j = 1; j < 7; j++) mx = fmaxf(mx, lg[j]);
        float se = 0.f;
#pragma unroll
        for (int j = 0; j < 7; j++) { lg[j] = expf(lg[j] - mx); se += lg[j]; }
        float inv = 1.f / se;
#pragma unroll
        for (int j = 0; j < 7; j++) out[(size_t)gb * 7 + j] = lg[j] * inv;

        float v = vb3[0];
#pragma unroll
        for (int k = 0; k < 32; k++) v += hp[32 + k] * vw3[k];
        out[(size_t)BATCH * 7 + gb] = tanhf(v);
    }
}

// =========================================================================
extern "C" void kernel_launch(void* const* d_in, const int* in_sizes, int n_in,
                              void* d_out, int out_size)
{
    const float* x        = (const float*)d_in[0];
    const float* conv_w   = (const float*)d_in[1];
    /* conv_b (d_in[2]) cancels exactly through batch-norm — unused */
    const float* bn_gamma = (const float*)d_in[3];
    const float* bn_beta  = (const float*)d_in[4];
    const float* pw1 = (const float*)d_in[5];
    const float* pb1 = (const float*)d_in[6];
    const float* pw2 = (const float*)d_in[7];
    const float* pb2 = (const float*)d_in[8];
    const float* pw3 = (const float*)d_in[9];
    const float* pb3 = (const float*)d_in[10];
    const float* vw1 = (const float*)d_in[11];
    const float* vb1 = (const float*)d_in[12];
    const float* vw2 = (const float*)d_in[13];
    const float* vb2 = (const float*)d_in[14];
    const float* vw3 = (const float*)d_in[15];
    const float* vb3 = (const float*)d_in[16];
    float* out = (float*)d_out;

    k_moments<<<NBLK_MOM, 256>>>(x);
    k_finalize<<<1, 256>>>(conv_w, bn_gamma, bn_beta);
    k_conv<<<BATCH, 256>>>(x);
    k_main<<<BATCH / MB, 256>>>(pw1, pb1, pw2, pb2, pw3, pb3,
                                vw1, vb1, vw2, vb2, vw3, vb3, out);
}

// round 3
// speedup vs baseline: 2.9641x; 2.9641x over previous
#include <cuda_runtime.h>
#include <cuda_fp16.h>
#include <cstdint>

#define BATCH 32768
#define NCH   256
#define FLAT  3072
#define NRED  152
#define NBLK_MOM 128
#define EPSV  1e-5f
#define CONV_BD 8

// ---------------- device scratch (no allocations allowed) ----------------
__device__ float g_part[NBLK_MOM][NRED];
__device__ float g_wscaled[NCH * 16];
__device__ float g_shift[NCH];
// h in permuted-K fp16 split form: index = board*3072 + (p*256 + c)
__device__ __half g_hhi[(size_t)BATCH * FLAT];
__device__ __half g_hlo[(size_t)BATCH * FLAT];
// fc1 weights, layout [k'][n] fp16 split (n<64 policy, n>=64 value)
__device__ __half g_w1hi[FLAT * 128];
__device__ __half g_w1lo[FLAT * 128];

// ======================= PTX helpers (baseline sm_80+) ==================
__device__ __forceinline__ uint32_t smem_u32(const void* p) {
    uint32_t a;
    asm("{ .reg .u64 t; cvta.to.shared.u64 t, %1; cvt.u32.u64 %0, t; }"
        : "=r"(a) : "l"(p));
    return a;
}
#define CP_ASYNC16(dst, src) \
    asm volatile("cp.async.cg.shared.global [%0], [%1], 16;" \
        :: "r"(dst), "l"(src) : "memory")
#define CP_COMMIT() asm volatile("cp.async.commit_group;" ::: "memory")
#define CP_WAIT1()  asm volatile("cp.async.wait_group 1;" ::: "memory")

__device__ __forceinline__ void ldsm_x4(uint32_t r[4], uint32_t addr) {
    asm volatile("ldmatrix.sync.aligned.m8n8.x4.shared.b16 {%0,%1,%2,%3}, [%4];"
        : "=r"(r[0]), "=r"(r[1]), "=r"(r[2]), "=r"(r[3]) : "r"(addr));
}
__device__ __forceinline__ void ldsm_x4t(uint32_t r[4], uint32_t addr) {
    asm volatile("ldmatrix.sync.aligned.m8n8.x4.trans.shared.b16 {%0,%1,%2,%3}, [%4];"
        : "=r"(r[0]), "=r"(r[1]), "=r"(r[2]), "=r"(r[3]) : "r"(addr));
}
__device__ __forceinline__ void mma16816(float& d0, float& d1, float& d2, float& d3,
                                         uint32_t a0, uint32_t a1, uint32_t a2, uint32_t a3,
                                         uint32_t b0, uint32_t b1) {
    asm volatile(
        "mma.sync.aligned.m16n8k16.row.col.f32.f16.f16.f32 "
        "{%0,%1,%2,%3}, {%4,%5,%6,%7}, {%8,%9}, {%0,%1,%2,%3};"
        : "+f"(d0), "+f"(d1), "+f"(d2), "+f"(d3)
        : "r"(a0), "r"(a1), "r"(a2), "r"(a3), "r"(b0), "r"(b1));
}

// =========================================================================
// K1: patch moments (unchanged — correctness proven in R1)
// =========================================================================
__global__ void k_moments(const float* __restrict__ x)
{
    int b = blockIdx.x * 256 + threadIdx.x;
    const float* xb = x + b * 42;
    float xv[42];
#pragma unroll
    for (int i = 0; i < 42; i++) xv[i] = xb[i];

    __shared__ float red[8][NRED];
    int lane = threadIdx.x & 31;
    int warp = threadIdx.x >> 5;

    int idx = 0;
#pragma unroll
    for (int k = 0; k < 16; k++) {
        float s = 0.f;
#pragma unroll
        for (int r = 0; r < 3; r++)
#pragma unroll
            for (int c = 0; c < 4; c++)
                s += xv[(r + (k >> 2)) * 7 + (c + (k & 3))];
#pragma unroll
        for (int o = 16; o; o >>= 1) s += __shfl_xor_sync(0xffffffffu, s, o);
        if (lane == 0) red[warp][idx] = s;
        idx++;
    }
#pragma unroll
    for (int k = 0; k < 16; k++) {
#pragma unroll
        for (int l = k; l < 16; l++) {
            float s = 0.f;
#pragma unroll
            for (int r = 0; r < 3; r++)
#pragma unroll
                for (int c = 0; c < 4; c++)
                    s += xv[(r + (k >> 2)) * 7 + (c + (k & 3))] *
                         xv[(r + (l >> 2)) * 7 + (c + (l & 3))];
#pragma unroll
            for (int o = 16; o; o >>= 1) s += __shfl_xor_sync(0xffffffffu, s, o);
            if (lane == 0) red[warp][idx] = s;
            idx++;
        }
    }
    __syncthreads();
    if (threadIdx.x < NRED) {
        float s = 0.f;
#pragma unroll
        for (int w = 0; w < 8; w++) s += red[w][threadIdx.x];
        g_part[blockIdx.x][threadIdx.x] = s;
    }
}

// =========================================================================
// K2: finalize BN fold (unchanged)
// =========================================================================
__global__ void k_finalize(const float* __restrict__ conv_w,
                           const float* __restrict__ bn_gamma,
                           const float* __restrict__ bn_beta)
{
    __shared__ float S[NRED];
    int t = threadIdx.x;
    if (t < NRED) {
        float s = 0.f;
        for (int bl = 0; bl < NBLK_MOM; bl++) s += g_part[bl][t];
        S[t] = s * (1.f / (12.f * (float)BATCH));
    }
    __syncthreads();
    if (t < NCH) {
        float w[16];
#pragma unroll
        for (int i = 0; i < 16; i++) w[i] = conv_w[t * 16 + i];
        float mraw = 0.f;
#pragma unroll
        for (int i = 0; i < 16; i++) mraw += w[i] * S[i];
        float q = 0.f;
        int idx = 16;
#pragma unroll
        for (int k = 0; k < 16; k++)
#pragma unroll
            for (int l = k; l < 16; l++) {
                float coef = (k == l) ? (w[k] * w[l]) : (2.f * w[k] * w[l]);
                q += coef * S[idx];
                idx++;
            }
        float var = q - mraw * mraw;
        float a = bn_gamma[t] * rsqrtf(var + EPSV);
#pragma unroll
        for (int i = 0; i < 16; i++) g_wscaled[t * 16 + i] = a * w[i];
        g_shift[t] = bn_beta[t] - a * mraw;
    }
}

// =========================================================================
// K_prep: W1 -> [k'][n] fp16-split.  kp = p*256+c maps to f = c*12+p.
// =========================================================================
__global__ void k_prep(const float* __restrict__ pw1, const float* __restrict__ vw1)
{
    int kp = blockIdx.x;       // 0..3071
    int n  = threadIdx.x;      // 0..127
    int p = kp >> 8, c = kp & 255;
    int f = c * 12 + p;
    float v = (n < 64) ? pw1[(size_t)f * 64 + n] : vw1[(size_t)f * 64 + (n - 64)];
    __half hi = __float2half_rn(v);
    __half lo = __float2half_rn(v - __half2float(hi));
    g_w1hi[(size_t)kp * 128 + n] = hi;
    g_w1lo[(size_t)kp * 128 + n] = lo;
}

// =========================================================================
// K3: conv + folded BN + ReLU -> fp16 split h, permuted layout.
// =========================================================================
__global__ __launch_bounds__(256) void k_conv(const float* __restrict__ x)
{
    int c  = threadIdx.x;
    int b0 = blockIdx.x * CONV_BD;
    __shared__ float xs[CONV_BD][42];
    for (int i = threadIdx.x; i < CONV_BD * 42; i += 256)
        ((float*)xs)[i] = x[(size_t)b0 * 42 + i];
    __syncthreads();

    float w[16];
    const float4* wp = reinterpret_cast<const float4*>(&g_wscaled[c * 16]);
#pragma unroll
    for (int i = 0; i < 4; i++) {
        float4 v = wp[i];
        w[i * 4 + 0] = v.x; w[i * 4 + 1] = v.y; w[i * 4 + 2] = v.z; w[i * 4 + 3] = v.w;
    }
    float shift = g_shift[c];

    for (int bd = 0; bd < CONV_BD; bd++) {
        float xv[42];
#pragma unroll
        for (int i = 0; i < 42; i++) xv[i] = xs[bd][i];
        size_t ob = (size_t)(b0 + bd) * FLAT + c;
#pragma unroll
        for (int p = 0; p < 12; p++) {
            int r = p >> 2, s = p & 3;
            float acc = shift;
#pragma unroll
            for (int i = 0; i < 4; i++)
#pragma unroll
                for (int j = 0; j < 4; j++)
                    acc += w[i * 4 + j] * xv[(r + i) * 7 + (s + j)];
            float v = fmaxf(acc, 0.f);
            __half hi = __float2half_rn(v);
            __half lo = __float2half_rn(v - __half2float(hi));
            g_hhi[ob + p * 256] = hi;
            g_hlo[ob + p * 256] = lo;
        }
    }
}

// =========================================================================
// K4: mma.sync GEMM (128 boards x 128 outs, K=3072, fp16 3-mma split) + heads
// Smem tile per buffer: Ahi[128][32] 8K | Alo 8K | Bhi[32][128] 8K | Blo 8K
// =========================================================================
#define KC3      32
#define NCHUNK3  (FLAT / KC3)    // 96
#define BUF_B3   32768
#define SMEM_DYN (99328 + 1024)

__global__ __launch_bounds__(256, 2) void k_main_mma(
    const float* __restrict__ pb1, const float* __restrict__ vb1,
    const float* __restrict__ pw2, const float* __restrict__ pb2,
    const float* __restrict__ pw3, const float* __restrict__ pb3,
    const float* __restrict__ vw2, const float* __restrict__ vb2,
    const float* __restrict__ vw3, const float* __restrict__ vb3,
    float* __restrict__ out)
{
    extern __shared__ char dyn_pool[];
    __shared__ float biasS[128];

    char* poolA = (char*)((((uintptr_t)dyn_pool) + 1023) & ~(uintptr_t)1023);
    const uint32_t pool_u = smem_u32(poolA);

    const int tid  = threadIdx.x;
    const int wid  = tid >> 5;
    const int lane = tid & 31;
    const int m0   = blockIdx.x * 128;
    const int wm   = wid & 3;       // warp m index (0..3) -> 32 rows
    const int wn   = wid >> 2;      // warp n index (0..1) -> 64 cols

    if (tid < 64)       biasS[tid] = pb1[tid];
    else if (tid < 128) biasS[tid] = vb1[tid - 64];

    // ---- cp.async loader lanes ----
    const int arow  = tid >> 1;            // 0..127
    const int ahalf = tid & 1;             // 16-half group
    const __half* gAhi = g_hhi + (size_t)(m0 + arow) * FLAT + ahalf * 16;
    const __half* gAlo = g_hlo + (size_t)(m0 + arow) * FLAT + ahalf * 16;
    const uint32_t swA = (uint32_t)((arow >> 1) & 3);
    const uint32_t oA0 = (uint32_t)arow * 64 + (((ahalf * 2 + 0) ^ swA) << 4);
    const uint32_t oA1 = (uint32_t)arow * 64 + (((ahalf * 2 + 1) ^ swA) << 4);

    const int brow = tid >> 3;             // 0..31 (k row in chunk)
    const int bc0  = (tid & 7) * 2;        // 16B chunk pair
    const __half* gBhi = g_w1hi + (size_t)brow * 128 + bc0 * 8;
    const __half* gBlo = g_w1lo + (size_t)brow * 128 + bc0 * 8;
    const uint32_t swB = (uint32_t)(brow & 7);
    const uint32_t oB0 = 16384u + (uint32_t)brow * 256 + (((bc0 + 0) ^ swB) << 4);
    const uint32_t oB1 = 16384u + (uint32_t)brow * 256 + (((bc0 + 1) ^ swB) << 4);

    float d[2][8][4];
#pragma unroll
    for (int mi = 0; mi < 2; mi++)
#pragma unroll
        for (int nj = 0; nj < 8; nj++)
#pragma unroll
            for (int q = 0; q < 4; q++) d[mi][nj][q] = 0.f;

    // ---- ldmatrix lane addressing constants ----
    const int a_r   = (lane & 15);         // row-in-frag
    const int a_hg  = (lane >> 4);         // k 8-group
    const int b_kl  = ((lane >> 3) & 1) * 8 + (lane & 7);  // k-in-16
    const int b_ng  = (lane >> 4);         // n 8-group

    // ---- prologue: issue chunks 0,1 ----
#pragma unroll
    for (int pc = 0; pc < 2; pc++) {
        const int kc = pc * KC3;
        const uint32_t sb = pool_u + pc * BUF_B3;
        CP_ASYNC16(sb + oA0, gAhi + kc);
        CP_ASYNC16(sb + oA1, gAhi + kc + 8);
        CP_ASYNC16(sb + 8192 + oA0, gAlo + kc);
        CP_ASYNC16(sb + 8192 + oA1, gAlo + kc + 8);
        CP_ASYNC16(sb + oB0, gBhi + (size_t)kc * 128);
        CP_ASYNC16(sb + oB1, gBhi + (size_t)kc * 128 + 8);
        CP_ASYNC16(sb + 8192 + oB0, gBlo + (size_t)kc * 128);
        CP_ASYNC16(sb + 8192 + oB1, gBlo + (size_t)kc * 128 + 8);
        CP_COMMIT();
    }

#pragma unroll 1
    for (int ch = 0; ch < NCHUNK3; ch++) {
        CP_WAIT1();
        __syncthreads();

        const uint32_t sb  = pool_u + (ch & 1) * BUF_B3;
        const uint32_t sbA = sb;
        const uint32_t sbB = sb + 16384;

#pragma unroll
        for (int ks = 0; ks < 2; ks++) {
            uint32_t ahi[2][4], alo[2][4];
#pragma unroll
            for (int mi = 0; mi < 2; mi++) {
                int row = wm * 32 + mi * 16 + a_r;
                uint32_t chunk = (uint32_t)(ks * 2 + a_hg);
                uint32_t off = (uint32_t)row * 64 + ((chunk ^ ((row >> 1) & 3)) << 4);
                ldsm_x4(ahi[mi], sbA + off);
                ldsm_x4(alo[mi], sbA + 8192 + off);
            }
#pragma unroll
            for (int ng = 0; ng < 4; ng++) {
                int k = ks * 16 + b_kl;
                uint32_t ncg = (uint32_t)(wn * 8 + ng * 2 + b_ng);
                uint32_t off = (uint32_t)k * 256 + ((ncg ^ (k & 7)) << 4);
                uint32_t bhi[4], blo[4];
                ldsm_x4t(bhi, sbB + off);
                ldsm_x4t(blo, sbB + 8192 + off);
#pragma unroll
                for (int mi = 0; mi < 2; mi++) {
                    float* d0 = d[mi][ng * 2];
                    float* d1 = d[mi][ng * 2 + 1];
                    mma16816(d0[0], d0[1], d0[2], d0[3],
                             ahi[mi][0], ahi[mi][1], ahi[mi][2], ahi[mi][3],
                             bhi[0], bhi[1]);
                    mma16816(d1[0], d1[1], d1[2], d1[3],
                             ahi[mi][0], ahi[mi][1], ahi[mi][2], ahi[mi][3],
                             bhi[2], bhi[3]);
                    mma16816(d0[0], d0[1], d0[2], d0[3],
                             alo[mi][0], alo[mi][1], alo[mi][2], alo[mi][3],
                             bhi[0], bhi[1]);
                    mma16816(d1[0], d1[1], d1[2], d1[3],
                             alo[mi][0], alo[mi][1], alo[mi][2], alo[mi][3],
                             bhi[2], bhi[3]);
                    mma16816(d0[0], d0[1], d0[2], d0[3],
                             ahi[mi][0], ahi[mi][1], ahi[mi][2], ahi[mi][3],
                             blo[0], blo[1]);
                    mma16816(d1[0], d1[1], d1[2], d1[3],
                             ahi[mi][0], ahi[mi][1], ahi[mi][2], ahi[mi][3],
                             blo[2], blo[3]);
                }
            }
        }
        __syncthreads();

        if (ch + 2 < NCHUNK3) {
            const int kc = (ch + 2) * KC3;
            CP_ASYNC16(sb + oA0, gAhi + kc);
            CP_ASYNC16(sb + oA1, gAhi + kc + 8);
            CP_ASYNC16(sb + 8192 + oA0, gAlo + kc);
            CP_ASYNC16(sb + 8192 + oA1, gAlo + kc + 8);
            CP_ASYNC16(sb + oB0, gBhi + (size_t)kc * 128);
            CP_ASYNC16(sb + oB1, gBhi + (size_t)kc * 128 + 8);
            CP_ASYNC16(sb + 8192 + oB0, gBlo + (size_t)kc * 128);
            CP_ASYNC16(sb + 8192 + oB1, gBlo + (size_t)kc * 128 + 8);
        }
        CP_COMMIT();
    }

    // ---------------- epilogue ----------------
    float* h1 = (float*)poolA;            // [128][129]
    float* h2 = (float*)(poolA + 66048);  // [128][65]

    {
        int g  = lane >> 2;
        int t2 = (lane & 3) * 2;
#pragma unroll
        for (int mi = 0; mi < 2; mi++) {
#pragma unroll
            for (int nj = 0; nj < 8; nj++) {
                int m = wm * 32 + mi * 16 + g;
                int n = wn * 64 + nj * 8 + t2;
                h1[m * 129 + n]           = fmaxf(d[mi][nj][0] + biasS[n], 0.f);
                h1[m * 129 + n + 1]       = fmaxf(d[mi][nj][1] + biasS[n + 1], 0.f);
                h1[(m + 8) * 129 + n]     = fmaxf(d[mi][nj][2] + biasS[n], 0.f);
                h1[(m + 8) * 129 + n + 1] = fmaxf(d[mi][nj][3] + biasS[n + 1], 0.f);
            }
        }
    }
    __syncthreads();

    // layer2: 128 boards x 64 outs (32 policy | 32 value)
#pragma unroll 1
    for (int it = 0; it < 32; it++) {
        int idx = it * 256 + tid;
        int bd = idx >> 6, o = idx & 63;
        int oo = o & 31;
        const float* h1b  = h1 + bd * 129 + ((o < 32) ? 0 : 64);
        const float* wmat = (o < 32) ? pw2 : vw2;
        float s = (o < 32) ? pb2[oo] : vb2[oo];
#pragma unroll 8
        for (int k = 0; k < 64; k++) s += h1b[k] * wmat[k * 32 + oo];
        h2[bd * 65 + o] = fmaxf(s, 0.f);
    }
    __syncthreads();

    // layer3 + softmax / tanh
    if (tid < 128) {
        int gb = m0 + tid;
        const float* hp = h2 + tid * 65;
        float lg[7];
#pragma unroll
        for (int j = 0; j < 7; j++) {
            float s = pb3[j];
#pragma unroll
            for (int k = 0; k < 32; k++) s += hp[k] * pw3[k * 7 + j];
            lg[j] = s;
        }
        float mx = lg[0];
#pragma unroll
        for (int j = 1; j < 7; j++) mx = fmaxf(mx, lg[j]);
        float se = 0.f;
#pragma unroll
        for (int j = 0; j < 7; j++) { lg[j] = expf(lg[j] - mx); se += lg[j]; }
        float inv = 1.f / se;
#pragma unroll
        for (int j = 0; j < 7; j++) out[(size_t)gb * 7 + j] = lg[j] * inv;

        float v = vb3[0];
#pragma unroll
        for (int k = 0; k < 32; k++) v += hp[32 + k] * vw3[k];
        out[(size_t)BATCH * 7 + gb] = tanhf(v);
    }
}

// =========================================================================
extern "C" void kernel_launch(void* const* d_in, const int* in_sizes, int n_in,
                              void* d_out, int out_size)
{
    const float* x        = (const float*)d_in[0];
    const float* conv_w   = (const float*)d_in[1];
    /* conv_b (d_in[2]) cancels exactly through batch-norm — unused */
    const float* bn_gamma = (const float*)d_in[3];
    const float* bn_beta  = (const float*)d_in[4];
    const float* pw1 = (const float*)d_in[5];
    const float* pb1 = (const float*)d_in[6];
    const float* pw2 = (const float*)d_in[7];
    const float* pb2 = (const float*)d_in[8];
    const float* pw3 = (const float*)d_in[9];
    const float* pb3 = (const float*)d_in[10];
    const float* vw1 = (const float*)d_in[11];
    const float* vb1 = (const float*)d_in[12];
    const float* vw2 = (const float*)d_in[13];
    const float* vb2 = (const float*)d_in[14];
    const float* vw3 = (const float*)d_in[15];
    const float* vb3 = (const float*)d_in[16];
    float* out = (float*)d_out;

    cudaFuncSetAttribute(k_main_mma, cudaFuncAttributeMaxDynamicSharedMemorySize, SMEM_DYN);

    k_moments<<<NBLK_MOM, 256>>>(x);
    k_finalize<<<1, 256>>>(conv_w, bn_gamma, bn_beta);
    k_prep<<<FLAT, 128>>>(pw1, vw1);
    k_conv<<<BATCH / CONV_BD, 256>>>(x);
    k_main_mma<<<BATCH / 128, 256, SMEM_DYN>>>(pb1, vb1, pw2, pb2, pw3, pb3,
                                               vw2, vb2, vw3, vb3, out);
}